// round 1
// baseline (speedup 1.0000x reference)
#include <cuda_runtime.h>
#include <cuda_bf16.h>

// Problem constants (fixed by dataset)
#define BATCH   4
#define DIN     4096
#define DOUT    11008
#define RANK    512

#define NCHUNK  64          // d-chunks for low-rank partial reduction
#define CHUNK_D (DIN / NCHUNK)   // 64

// Scratch (allocation-free rule: __device__ globals)
__device__ float  g_xm[BATCH * DIN];          // masked input, SoA [b][d]   (64 KB)
__device__ float4 g_lr_part[NCHUNK * RANK];   // per-chunk partial lr       (512 KB)
__device__ float  g_lrs[BATCH * RANK];        // S-scaled lr, SoA [b][r]    (8 KB)

// ---------------------------------------------------------------------------
// Kernel 1: mask split + per-chunk low-rank partial   (grid NCHUNK x 512)
//   xm = x * mask ; xc = x * (1-mask)
//   lr_part[c][r][b] = sum_{d in chunk c} xc[b][d] * V[d][r]
// ---------------------------------------------------------------------------
__global__ __launch_bounds__(512) void k_mask_lr(
    const float* __restrict__ input,
    const float* __restrict__ V,
    const float* __restrict__ scale,
    const float* __restrict__ thr)
{
    __shared__ float4 sxc[CHUNK_D];   // complement input per d, vector over b

    const int c = blockIdx.x;
    const int t = threadIdx.x;

    if (t < CHUNK_D) {
        const int d = c * CHUNK_D + t;
        const float th = thr[0];
        const float sc = scale[d];
        float x0 = input[0 * DIN + d];
        float x1 = input[1 * DIN + d];
        float x2 = input[2 * DIN + d];
        float x3 = input[3 * DIN + d];
        bool m0 = fabsf(x0 * sc) > th;
        bool m1 = fabsf(x1 * sc) > th;
        bool m2 = fabsf(x2 * sc) > th;
        bool m3 = fabsf(x3 * sc) > th;
        // masked part -> g_xm (SoA by batch), complement -> smem
        g_xm[0 * DIN + d] = m0 ? x0 : 0.0f;
        g_xm[1 * DIN + d] = m1 ? x1 : 0.0f;
        g_xm[2 * DIN + d] = m2 ? x2 : 0.0f;
        g_xm[3 * DIN + d] = m3 ? x3 : 0.0f;
        float4 xc;
        xc.x = m0 ? 0.0f : x0;
        xc.y = m1 ? 0.0f : x1;
        xc.z = m2 ? 0.0f : x2;
        xc.w = m3 ? 0.0f : x3;
        sxc[t] = xc;
    }
    __syncthreads();

    const int r = t;   // 512 threads == RANK
    const float* __restrict__ Vc = V + (size_t)(c * CHUNK_D) * RANK + r;
    float4 acc = make_float4(0.f, 0.f, 0.f, 0.f);
#pragma unroll 8
    for (int i = 0; i < CHUNK_D; i++) {
        float  v = Vc[(size_t)i * RANK];   // coalesced over r
        float4 x = sxc[i];                 // smem broadcast
        acc.x += v * x.x;
        acc.y += v * x.y;
        acc.z += v * x.z;
        acc.w += v * x.w;
    }
    g_lr_part[c * RANK + r] = acc;
}

// ---------------------------------------------------------------------------
// Kernel 2: reduce partials over chunks, fold S   (grid 8 x 64)
//   g_lrs[b][r] = S[r] * sum_c lr_part[c][r][b]
// ---------------------------------------------------------------------------
__global__ __launch_bounds__(64) void k_lr_reduce(const float* __restrict__ S)
{
    const int r = blockIdx.x * 64 + threadIdx.x;   // [0,512)
    float4 acc = make_float4(0.f, 0.f, 0.f, 0.f);
#pragma unroll 8
    for (int c = 0; c < NCHUNK; c++) {
        float4 p = g_lr_part[c * RANK + r];
        acc.x += p.x; acc.y += p.y; acc.z += p.z; acc.w += p.w;
    }
    const float s = S[r];
    g_lrs[0 * RANK + r] = acc.x * s;
    g_lrs[1 * RANK + r] = acc.y * s;
    g_lrs[2 * RANK + r] = acc.z * s;
    g_lrs[3 * RANK + r] = acc.w * s;
}

// ---------------------------------------------------------------------------
// Kernel 3: fused GEMV  out[b][o] = xm[b]·W[o] + lrs[b]·U[o] + bias[o]
//   256 thr/block, 8 warps, 4 consecutive rows per warp -> 32 rows/block
//   grid = DOUT/32 = 344 blocks; 72 KB dyn smem (xm SoA + lrs SoA);
//   3 CTAs/SM -> 444 slots >= 344 -> single fully-resident wave.
// ---------------------------------------------------------------------------
__global__ __launch_bounds__(256, 3) void k_gemv(
    const float* __restrict__ W,
    const float* __restrict__ bias,
    const float* __restrict__ U,
    float* __restrict__ out)
{
    extern __shared__ float smem[];   // [0,16384): xm SoA, [16384,18432): lrs SoA

    // cooperative fill (linear copy, both global buffers are already SoA)
    {
        float4*       s4  = reinterpret_cast<float4*>(smem);
        const float4* gx4 = reinterpret_cast<const float4*>(g_xm);
        const float4* gl4 = reinterpret_cast<const float4*>(g_lrs);
#pragma unroll
        for (int i = threadIdx.x; i < (BATCH * DIN) / 4; i += 256)
            s4[i] = gx4[i];
#pragma unroll
        for (int i = threadIdx.x; i < (BATCH * RANK) / 4; i += 256)
            s4[(BATCH * DIN) / 4 + i] = gl4[i];
    }
    __syncthreads();

    const int wid  = threadIdx.x >> 5;
    const int lane = threadIdx.x & 31;
    const int o0   = blockIdx.x * 32 + wid * 4;   // 4 consecutive rows per warp

    const float4* __restrict__ Wp = reinterpret_cast<const float4*>(W + (size_t)o0 * DIN);
    const float4* __restrict__ sx0 = reinterpret_cast<const float4*>(smem);
    const float4* __restrict__ sx1 = reinterpret_cast<const float4*>(smem + DIN);
    const float4* __restrict__ sx2 = reinterpret_cast<const float4*>(smem + 2 * DIN);
    const float4* __restrict__ sx3 = reinterpret_cast<const float4*>(smem + 3 * DIN);

    float acc[4][4];
#pragma unroll
    for (int r = 0; r < 4; r++)
#pragma unroll
        for (int b = 0; b < 4; b++) acc[r][b] = 0.0f;

    // ---- dominant loop: stream W, reuse conflict-free SoA xm from smem ----
#pragma unroll 2
    for (int k = 0; k < (DIN / 4) / 32; k++) {       // 32 iterations
        const int i = lane + 32 * k;
        const float4 x0 = sx0[i];
        const float4 x1 = sx1[i];
        const float4 x2 = sx2[i];
        const float4 x3 = sx3[i];
#pragma unroll
        for (int r = 0; r < 4; r++) {
            const float4 w4 = Wp[(size_t)r * (DIN / 4) + i];   // LDG.128, coalesced
            acc[r][0] += w4.x * x0.x + w4.y * x0.y + w4.z * x0.z + w4.w * x0.w;
            acc[r][1] += w4.x * x1.x + w4.y * x1.y + w4.z * x1.z + w4.w * x1.w;
            acc[r][2] += w4.x * x2.x + w4.y * x2.y + w4.z * x2.z + w4.w * x2.w;
            acc[r][3] += w4.x * x3.x + w4.y * x3.y + w4.z * x3.z + w4.w * x3.w;
        }
    }

    // ---- low-rank epilogue: U rows x S-scaled lr ----
    {
        const float4* __restrict__ Up = reinterpret_cast<const float4*>(U + (size_t)o0 * RANK);
        const float4* __restrict__ sl0 = reinterpret_cast<const float4*>(smem + BATCH * DIN);
        const float4* __restrict__ sl1 = sl0 + RANK / 4;
        const float4* __restrict__ sl2 = sl0 + 2 * (RANK / 4);
        const float4* __restrict__ sl3 = sl0 + 3 * (RANK / 4);
#pragma unroll
        for (int k = 0; k < (RANK / 4) / 32; k++) {   // 4 iterations
            const int i = lane + 32 * k;
            const float4 l0 = sl0[i];
            const float4 l1 = sl1[i];
            const float4 l2 = sl2[i];
            const float4 l3 = sl3[i];
#pragma unroll
            for (int r = 0; r < 4; r++) {
                const float4 u4 = Up[(size_t)r * (RANK / 4) + i];
                acc[r][0] += u4.x * l0.x + u4.y * l0.y + u4.z * l0.z + u4.w * l0.w;
                acc[r][1] += u4.x * l1.x + u4.y * l1.y + u4.z * l1.z + u4.w * l1.w;
                acc[r][2] += u4.x * l2.x + u4.y * l2.y + u4.z * l2.z + u4.w * l2.w;
                acc[r][3] += u4.x * l3.x + u4.y * l3.y + u4.z * l3.z + u4.w * l3.w;
            }
        }
    }

    // ---- warp reduction + write ----
#pragma unroll
    for (int r = 0; r < 4; r++)
#pragma unroll
        for (int b = 0; b < 4; b++) {
            float v = acc[r][b];
            v += __shfl_xor_sync(0xffffffffu, v, 16);
            v += __shfl_xor_sync(0xffffffffu, v, 8);
            v += __shfl_xor_sync(0xffffffffu, v, 4);
            v += __shfl_xor_sync(0xffffffffu, v, 2);
            v += __shfl_xor_sync(0xffffffffu, v, 1);
            acc[r][b] = v;
        }

    if (lane == 0) {
#pragma unroll
        for (int r = 0; r < 4; r++) {
            const float bs = bias[o0 + r];
#pragma unroll
            for (int b = 0; b < 4; b++)
                out[(size_t)b * DOUT + o0 + r] = acc[r][b] + bs;
        }
    }
}

// ---------------------------------------------------------------------------
extern "C" void kernel_launch(void* const* d_in, const int* in_sizes, int n_in,
                              void* d_out, int out_size)
{
    const float* input  = (const float*)d_in[0];
    const float* weight = (const float*)d_in[1];
    const float* bias   = (const float*)d_in[2];
    const float* U      = (const float*)d_in[3];
    const float* S      = (const float*)d_in[4];
    const float* V      = (const float*)d_in[5];
    const float* scale  = (const float*)d_in[6];
    const float* thresh = (const float*)d_in[7];
    float* out = (float*)d_out;

    const int smem_bytes = (BATCH * DIN + BATCH * RANK) * (int)sizeof(float); // 73728
    cudaFuncSetAttribute(k_gemv, cudaFuncAttributeMaxDynamicSharedMemorySize, smem_bytes);

    k_mask_lr<<<NCHUNK, 512>>>(input, V, scale, thresh);
    k_lr_reduce<<<RANK / 64, 64>>>(S);
    k_gemv<<<DOUT / 32, 256, smem_bytes>>>(weight, bias, U, out);
}

// round 4
// speedup vs baseline: 1.0281x; 1.0281x over previous
#include <cuda_runtime.h>
#include <cuda_bf16.h>

// Problem constants (fixed by dataset)
#define BATCH   4
#define DIN     4096
#define DOUT    11008
#define RANK    512

#define NCHUNK  256               // d-chunks for low-rank partial reduction
#define CHUNK_D (DIN / NCHUNK)    // 16

// Scratch (allocation-free rule: __device__ globals)
__device__ float  g_xm[BATCH * DIN];          // masked input, SoA [b][d]   (64 KB)
__device__ float4 g_lr_part[NCHUNK * RANK];   // per-chunk partial lr       (2 MB)
__device__ float  g_lrs[BATCH * RANK];        // S-scaled lr, SoA [b][r]    (8 KB)

// ---------------------------------------------------------------------------
// Kernel 1: mask split + per-chunk low-rank partial   (grid NCHUNK x 512)
//   xm = x * mask ; xc = x * (1-mask)
//   lr_part[c][r] = (over batch) sum_{d in chunk c} xc[b][d] * V[d][r]
//   Fully-unrolled 16-deep MLP per thread; 256 blocks keep every SM busy.
// ---------------------------------------------------------------------------
__global__ __launch_bounds__(512) void k_mask_lr(
    const float* __restrict__ input,
    const float* __restrict__ V,
    const float* __restrict__ scale,
    const float* __restrict__ thr)
{
    __shared__ float4 sxc[CHUNK_D];   // complement input per d, vector over b

    const int c = blockIdx.x;
    const int t = threadIdx.x;

    if (t < CHUNK_D) {
        const int d = c * CHUNK_D + t;
        const float th = thr[0];
        const float sc = scale[d];
        float x0 = input[0 * DIN + d];
        float x1 = input[1 * DIN + d];
        float x2 = input[2 * DIN + d];
        float x3 = input[3 * DIN + d];
        bool m0 = fabsf(x0 * sc) > th;
        bool m1 = fabsf(x1 * sc) > th;
        bool m2 = fabsf(x2 * sc) > th;
        bool m3 = fabsf(x3 * sc) > th;
        g_xm[0 * DIN + d] = m0 ? x0 : 0.0f;
        g_xm[1 * DIN + d] = m1 ? x1 : 0.0f;
        g_xm[2 * DIN + d] = m2 ? x2 : 0.0f;
        g_xm[3 * DIN + d] = m3 ? x3 : 0.0f;
        float4 xc;
        xc.x = m0 ? 0.0f : x0;
        xc.y = m1 ? 0.0f : x1;
        xc.z = m2 ? 0.0f : x2;
        xc.w = m3 ? 0.0f : x3;
        sxc[t] = xc;
    }
    __syncthreads();

    const int r = t;   // 512 threads == RANK
    const float* __restrict__ Vc = V + (size_t)(c * CHUNK_D) * RANK + r;
    float4 acc = make_float4(0.f, 0.f, 0.f, 0.f);
#pragma unroll
    for (int i = 0; i < CHUNK_D; i++) {
        float  v = Vc[(size_t)i * RANK];   // coalesced over r
        float4 x = sxc[i];                 // smem broadcast
        acc.x += v * x.x;
        acc.y += v * x.y;
        acc.z += v * x.z;
        acc.w += v * x.w;
    }
    g_lr_part[c * RANK + r] = acc;
}

// ---------------------------------------------------------------------------
// Kernel 2: reduce partials over 256 chunks, fold S   (grid 16 x 256)
//   Block handles 32 r values; 8 chunk-lanes per r (one per warp row),
//   each lane sums 32 chunks, then smem reduction of the 8 partials.
// ---------------------------------------------------------------------------
__global__ __launch_bounds__(256) void k_lr_reduce(const float* __restrict__ S)
{
    __shared__ float4 sred[256];

    const int tid   = threadIdx.x;
    const int rloc  = tid & 31;                 // r within block
    const int clane = tid >> 5;                 // chunk lane [0,8)
    const int r     = blockIdx.x * 32 + rloc;

    float4 acc = make_float4(0.f, 0.f, 0.f, 0.f);
#pragma unroll 8
    for (int j = 0; j < NCHUNK / 8; j++) {
        float4 p = g_lr_part[(clane + 8 * j) * RANK + r];  // coalesced over r
        acc.x += p.x; acc.y += p.y; acc.z += p.z; acc.w += p.w;
    }
    sred[tid] = acc;
    __syncthreads();

    if (tid < 32) {
        float4 a = sred[tid];
#pragma unroll
        for (int l = 1; l < 8; l++) {
            float4 p = sred[tid + 32 * l];
            a.x += p.x; a.y += p.y; a.z += p.z; a.w += p.w;
        }
        const float s = S[r];
        g_lrs[0 * RANK + r] = a.x * s;
        g_lrs[1 * RANK + r] = a.y * s;
        g_lrs[2 * RANK + r] = a.z * s;
        g_lrs[3 * RANK + r] = a.w * s;
    }
}

// ---------------------------------------------------------------------------
// Kernel 3: fused GEMV  out[b][o] = xm[b]·W[o] + lrs[b]·U[o] + bias[o]
//   128 thr/block, 4 warps, 8 consecutive rows per warp -> 32 rows/block.
//   8 rows/warp halves smem-read pressure per DRAM byte (LDS:LDG = 4:8)
//   so the shared 128 B/cyc L1 port no longer caps DRAM streaming.
//   grid = DOUT/32 = 344 blocks; 72 KB dyn smem; 3 CTAs/SM.
// ---------------------------------------------------------------------------
__global__ __launch_bounds__(128, 3) void k_gemv(
    const float* __restrict__ W,
    const float* __restrict__ bias,
    const float* __restrict__ U,
    float* __restrict__ out)
{
    extern __shared__ float smem[];   // [0,16384): xm SoA, [16384,18432): lrs SoA

    // cooperative fill (both global buffers already SoA; L2-resident)
    {
        float4*       s4  = reinterpret_cast<float4*>(smem);
        const float4* gx4 = reinterpret_cast<const float4*>(g_xm);
        const float4* gl4 = reinterpret_cast<const float4*>(g_lrs);
        for (int i = threadIdx.x; i < (BATCH * DIN) / 4; i += 128)
            s4[i] = gx4[i];
        for (int i = threadIdx.x; i < (BATCH * RANK) / 4; i += 128)
            s4[(BATCH * DIN) / 4 + i] = gl4[i];
    }
    __syncthreads();

    const int wid  = threadIdx.x >> 5;
    const int lane = threadIdx.x & 31;
    const int o0   = blockIdx.x * 32 + wid * 8;   // 8 consecutive rows per warp

    const float4* __restrict__ Wp  = reinterpret_cast<const float4*>(W + (size_t)o0 * DIN);
    const float4* __restrict__ sx0 = reinterpret_cast<const float4*>(smem);
    const float4* __restrict__ sx1 = reinterpret_cast<const float4*>(smem + DIN);
    const float4* __restrict__ sx2 = reinterpret_cast<const float4*>(smem + 2 * DIN);
    const float4* __restrict__ sx3 = reinterpret_cast<const float4*>(smem + 3 * DIN);

    float acc[8][4];
#pragma unroll
    for (int r = 0; r < 8; r++)
#pragma unroll
        for (int b = 0; b < 4; b++) acc[r][b] = 0.0f;

    // ---- dominant loop: stream W, reuse conflict-free SoA xm from smem ----
#pragma unroll 2
    for (int k = 0; k < (DIN / 4) / 32; k++) {       // 32 iterations
        const int i = lane + 32 * k;
        const float4 x0 = sx0[i];
        const float4 x1 = sx1[i];
        const float4 x2 = sx2[i];
        const float4 x3 = sx3[i];
#pragma unroll
        for (int r = 0; r < 8; r++) {
            const float4 w4 = Wp[(size_t)r * (DIN / 4) + i];   // LDG.128, coalesced
            acc[r][0] += w4.x * x0.x + w4.y * x0.y + w4.z * x0.z + w4.w * x0.w;
            acc[r][1] += w4.x * x1.x + w4.y * x1.y + w4.z * x1.z + w4.w * x1.w;
            acc[r][2] += w4.x * x2.x + w4.y * x2.y + w4.z * x2.z + w4.w * x2.w;
            acc[r][3] += w4.x * x3.x + w4.y * x3.y + w4.z * x3.z + w4.w * x3.w;
        }
    }

    // ---- low-rank epilogue: U rows x S-scaled lr ----
    {
        const float4* __restrict__ Up  = reinterpret_cast<const float4*>(U + (size_t)o0 * RANK);
        const float4* __restrict__ sl0 = reinterpret_cast<const float4*>(smem + BATCH * DIN);
        const float4* __restrict__ sl1 = sl0 + RANK / 4;
        const float4* __restrict__ sl2 = sl0 + 2 * (RANK / 4);
        const float4* __restrict__ sl3 = sl0 + 3 * (RANK / 4);
#pragma unroll
        for (int k = 0; k < (RANK / 4) / 32; k++) {   // 4 iterations
            const int i = lane + 32 * k;
            const float4 l0 = sl0[i];
            const float4 l1 = sl1[i];
            const float4 l2 = sl2[i];
            const float4 l3 = sl3[i];
#pragma unroll
            for (int r = 0; r < 8; r++) {
                const float4 u4 = Up[(size_t)r * (RANK / 4) + i];
                acc[r][0] += u4.x * l0.x + u4.y * l0.y + u4.z * l0.z + u4.w * l0.w;
                acc[r][1] += u4.x * l1.x + u4.y * l1.y + u4.z * l1.z + u4.w * l1.w;
                acc[r][2] += u4.x * l2.x + u4.y * l2.y + u4.z * l2.z + u4.w * l2.w;
                acc[r][3] += u4.x * l3.x + u4.y * l3.y + u4.z * l3.z + u4.w * l3.w;
            }
        }
    }

    // ---- warp reduction + write ----
#pragma unroll
    for (int r = 0; r < 8; r++)
#pragma unroll
        for (int b = 0; b < 4; b++) {
            float v = acc[r][b];
            v += __shfl_xor_sync(0xffffffffu, v, 16);
            v += __shfl_xor_sync(0xffffffffu, v, 8);
            v += __shfl_xor_sync(0xffffffffu, v, 4);
            v += __shfl_xor_sync(0xffffffffu, v, 2);
            v += __shfl_xor_sync(0xffffffffu, v, 1);
            acc[r][b] = v;
        }

    if (lane == 0) {
#pragma unroll
        for (int r = 0; r < 8; r++) {
            const float bs = bias[o0 + r];
#pragma unroll
            for (int b = 0; b < 4; b++)
                out[(size_t)b * DOUT + o0 + r] = acc[r][b] + bs;
        }
    }
}

// ---------------------------------------------------------------------------
extern "C" void kernel_launch(void* const* d_in, const int* in_sizes, int n_in,
                              void* d_out, int out_size)
{
    const float* input  = (const float*)d_in[0];
    const float* weight = (const float*)d_in[1];
    const float* bias   = (const float*)d_in[2];
    const float* U      = (const float*)d_in[3];
    const float* S      = (const float*)d_in[4];
    const float* V      = (const float*)d_in[5];
    const float* scale  = (const float*)d_in[6];
    const float* thresh = (const float*)d_in[7];
    float* out = (float*)d_out;

    const int smem_bytes = (BATCH * DIN + BATCH * RANK) * (int)sizeof(float); // 73728
    cudaFuncSetAttribute(k_gemv, cudaFuncAttributeMaxDynamicSharedMemorySize, smem_bytes);

    k_mask_lr<<<NCHUNK, 512>>>(input, V, scale, thresh);
    k_lr_reduce<<<RANK / 32, 256>>>(S);
    k_gemv<<<DOUT / 32, 128, smem_bytes>>>(weight, bias, U, out);
}

// round 5
// speedup vs baseline: 1.0322x; 1.0040x over previous
#include <cuda_runtime.h>
#include <cuda_bf16.h>
#include <cstdint>

// Problem constants (fixed by dataset)
#define BATCH   4
#define DIN     4096
#define DOUT    11008
#define RANK    512

#define NCHUNK  128               // d-chunks for low-rank partial reduction
#define CHUNK_D (DIN / NCHUNK)    // 32
#define NGRP    4                 // i-groups per chunk (thread-block sub-split)
#define NPART   (NCHUNK * NGRP)   // 512 partial slots

// Scratch (allocation-free rule: __device__ globals)
__device__ float  g_xm[BATCH * DIN];          // masked input, SoA [b][d]   (64 KB)
__device__ float4 g_lr_part[NPART * RANK];    // per-part lr, batch-vector  (4 MB)
__device__ float  g_lrs[BATCH * RANK];        // S-scaled lr, SoA [b][r]    (8 KB)

__device__ __forceinline__ void cp_async16(void* s, const void* g) {
    uint32_t sa = (uint32_t)__cvta_generic_to_shared(s);
    asm volatile("cp.async.cg.shared.global [%0], [%1], 16;\n" :: "r"(sa), "l"(g));
}

// ---------------------------------------------------------------------------
// Kernel 1: mask split + per-chunk low-rank partial   (grid NCHUNK x 512)
//   Thread layout: rq = tid&127 (r-quad, float4 over RANK), ig = tid>>7.
//   Each thread: 8 fully-unrolled float4 V loads (128 B in flight) over
//   rows d = c*32 + 4*j + ig. Writes 4 batch-vector partials per thread.
// ---------------------------------------------------------------------------
__global__ __launch_bounds__(512) void k_mask_lr(
    const float* __restrict__ input,
    const float* __restrict__ V,
    const float* __restrict__ scale,
    const float* __restrict__ thr)
{
    __shared__ float4 sxc[CHUNK_D];   // complement input per d, vector over b

    const int c = blockIdx.x;
    const int t = threadIdx.x;

    if (t < CHUNK_D) {
        const int d = c * CHUNK_D + t;
        const float th = thr[0];
        const float sc = scale[d];
        float x0 = input[0 * DIN + d];
        float x1 = input[1 * DIN + d];
        float x2 = input[2 * DIN + d];
        float x3 = input[3 * DIN + d];
        bool m0 = fabsf(x0 * sc) > th;
        bool m1 = fabsf(x1 * sc) > th;
        bool m2 = fabsf(x2 * sc) > th;
        bool m3 = fabsf(x3 * sc) > th;
        g_xm[0 * DIN + d] = m0 ? x0 : 0.0f;
        g_xm[1 * DIN + d] = m1 ? x1 : 0.0f;
        g_xm[2 * DIN + d] = m2 ? x2 : 0.0f;
        g_xm[3 * DIN + d] = m3 ? x3 : 0.0f;
        float4 xc;
        xc.x = m0 ? 0.0f : x0;
        xc.y = m1 ? 0.0f : x1;
        xc.z = m2 ? 0.0f : x2;
        xc.w = m3 ? 0.0f : x3;
        sxc[t] = xc;
    }
    __syncthreads();

    const int rq = t & 127;          // float4 index over RANK (r = 4*rq..4*rq+3)
    const int ig = t >> 7;           // i-group [0,4)
    const float4* __restrict__ V4 = reinterpret_cast<const float4*>(V);

    // batch prefetch all 8 V rows for this thread (independent LDG.128s)
    float4 v[8];
#pragma unroll
    for (int j = 0; j < 8; j++) {
        const int d = c * CHUNK_D + 4 * j + ig;
        v[j] = V4[(size_t)d * (RANK / 4) + rq];
    }

    float4 a0 = make_float4(0.f, 0.f, 0.f, 0.f);   // r-component 0, batch vec
    float4 a1 = a0, a2 = a0, a3 = a0;
#pragma unroll
    for (int j = 0; j < 8; j++) {
        const float4 xb = sxc[4 * j + ig];         // batches, smem broadcast
        a0.x += v[j].x * xb.x; a0.y += v[j].x * xb.y; a0.z += v[j].x * xb.z; a0.w += v[j].x * xb.w;
        a1.x += v[j].y * xb.x; a1.y += v[j].y * xb.y; a1.z += v[j].y * xb.z; a1.w += v[j].y * xb.w;
        a2.x += v[j].z * xb.x; a2.y += v[j].z * xb.y; a2.z += v[j].z * xb.z; a2.w += v[j].z * xb.w;
        a3.x += v[j].w * xb.x; a3.y += v[j].w * xb.y; a3.z += v[j].w * xb.z; a3.w += v[j].w * xb.w;
    }

    const int p = c * NGRP + ig;                   // partial slot [0,512)
    g_lr_part[(size_t)p * RANK + 4 * rq + 0] = a0;
    g_lr_part[(size_t)p * RANK + 4 * rq + 1] = a1;
    g_lr_part[(size_t)p * RANK + 4 * rq + 2] = a2;
    g_lr_part[(size_t)p * RANK + 4 * rq + 3] = a3;
}

// ---------------------------------------------------------------------------
// Kernel 2: reduce partials over NPART slots, fold S   (grid 16 x 256)
//   Block handles 32 r; 8 part-lanes per r, 64 parts each; smem reduce.
// ---------------------------------------------------------------------------
__global__ __launch_bounds__(256) void k_lr_reduce(const float* __restrict__ S)
{
    __shared__ float4 sred[256];

    const int tid   = threadIdx.x;
    const int rloc  = tid & 31;
    const int clane = tid >> 5;                 // part lane [0,8)
    const int r     = blockIdx.x * 32 + rloc;

    float4 acc = make_float4(0.f, 0.f, 0.f, 0.f);
#pragma unroll 8
    for (int j = 0; j < NPART / 8; j++) {
        float4 p = g_lr_part[(size_t)(clane + 8 * j) * RANK + r];  // coalesced over r
        acc.x += p.x; acc.y += p.y; acc.z += p.z; acc.w += p.w;
    }
    sred[tid] = acc;
    __syncthreads();

    if (tid < 32) {
        float4 a = sred[tid];
#pragma unroll
        for (int l = 1; l < 8; l++) {
            float4 p = sred[tid + 32 * l];
            a.x += p.x; a.y += p.y; a.z += p.z; a.w += p.w;
        }
        const float s = S[r];
        g_lrs[0 * RANK + r] = a.x * s;
        g_lrs[1 * RANK + r] = a.y * s;
        g_lrs[2 * RANK + r] = a.z * s;
        g_lrs[3 * RANK + r] = a.w * s;
    }
}

// ---------------------------------------------------------------------------
// Kernel 3: fused GEMV  out[b][o] = xm[b]·W[o] + lrs[b]·U[o] + bias[o]
//   128 thr/block, 4 warps, 8 rows/warp, grid 344, 3 CTAs/SM.
//   cp.async smem fill (no register dependency -> no startup stall) and a
//   register double-buffer on W: ~16 LDG.128 in flight per warp so DRAM
//   latency stops being the binding constraint.
// ---------------------------------------------------------------------------
__global__ __launch_bounds__(128, 3) void k_gemv(
    const float* __restrict__ W,
    const float* __restrict__ bias,
    const float* __restrict__ U,
    float* __restrict__ out)
{
    extern __shared__ float smem[];   // [0,16384): xm SoA, [16384,18432): lrs SoA

    // ---- async smem fill: 36 cp.async per thread, issued back-to-back ----
    {
        float4*       s4  = reinterpret_cast<float4*>(smem);
        const float4* gx4 = reinterpret_cast<const float4*>(g_xm);
        const float4* gl4 = reinterpret_cast<const float4*>(g_lrs);
#pragma unroll
        for (int j = 0; j < (BATCH * DIN) / 4 / 128; j++) {      // 32
            const int i = threadIdx.x + 128 * j;
            cp_async16(&s4[i], &gx4[i]);
        }
#pragma unroll
        for (int j = 0; j < (BATCH * RANK) / 4 / 128; j++) {     // 4
            const int i = threadIdx.x + 128 * j;
            cp_async16(&s4[(BATCH * DIN) / 4 + i], &gl4[i]);
        }
        asm volatile("cp.async.commit_group;\n" ::: "memory");
    }

    const int wid  = threadIdx.x >> 5;
    const int lane = threadIdx.x & 31;
    const int o0   = blockIdx.x * 32 + wid * 8;   // 8 consecutive rows per warp

    const float4* __restrict__ Wp = reinterpret_cast<const float4*>(W + (size_t)o0 * DIN);

    // preload first W iteration while the cp.async fill is in flight
    float4 wA[8];
#pragma unroll
    for (int r = 0; r < 8; r++)
        wA[r] = Wp[(size_t)r * (DIN / 4) + lane];

    asm volatile("cp.async.wait_group 0;\n" ::: "memory");
    __syncthreads();

    const float4* __restrict__ sx0 = reinterpret_cast<const float4*>(smem);
    const float4* __restrict__ sx1 = reinterpret_cast<const float4*>(smem + DIN);
    const float4* __restrict__ sx2 = reinterpret_cast<const float4*>(smem + 2 * DIN);
    const float4* __restrict__ sx3 = reinterpret_cast<const float4*>(smem + 3 * DIN);

    float acc[8][4];
#pragma unroll
    for (int r = 0; r < 8; r++)
#pragma unroll
        for (int b = 0; b < 4; b++) acc[r][b] = 0.0f;

    // ---- dominant loop: software-pipelined W stream (double buffer) ----
#pragma unroll 2
    for (int k = 0; k < 31; k++) {
        float4 wB[8];
        const int inx = lane + 32 * (k + 1);
#pragma unroll
        for (int r = 0; r < 8; r++)
            wB[r] = Wp[(size_t)r * (DIN / 4) + inx];    // prefetch next iter

        const int i = lane + 32 * k;
        const float4 x0 = sx0[i];
        const float4 x1 = sx1[i];
        const float4 x2 = sx2[i];
        const float4 x3 = sx3[i];
#pragma unroll
        for (int r = 0; r < 8; r++) {
            acc[r][0] += wA[r].x * x0.x + wA[r].y * x0.y + wA[r].z * x0.z + wA[r].w * x0.w;
            acc[r][1] += wA[r].x * x1.x + wA[r].y * x1.y + wA[r].z * x1.z + wA[r].w * x1.w;
            acc[r][2] += wA[r].x * x2.x + wA[r].y * x2.y + wA[r].z * x2.z + wA[r].w * x2.w;
            acc[r][3] += wA[r].x * x3.x + wA[r].y * x3.y + wA[r].z * x3.z + wA[r].w * x3.w;
        }
#pragma unroll
        for (int r = 0; r < 8; r++) wA[r] = wB[r];      // renamed away by unroll 2
    }
    {   // last iteration (k = 31)
        const int i = lane + 32 * 31;
        const float4 x0 = sx0[i];
        const float4 x1 = sx1[i];
        const float4 x2 = sx2[i];
        const float4 x3 = sx3[i];
#pragma unroll
        for (int r = 0; r < 8; r++) {
            acc[r][0] += wA[r].x * x0.x + wA[r].y * x0.y + wA[r].z * x0.z + wA[r].w * x0.w;
            acc[r][1] += wA[r].x * x1.x + wA[r].y * x1.y + wA[r].z * x1.z + wA[r].w * x1.w;
            acc[r][2] += wA[r].x * x2.x + wA[r].y * x2.y + wA[r].z * x2.z + wA[r].w * x2.w;
            acc[r][3] += wA[r].x * x3.x + wA[r].y * x3.y + wA[r].z * x3.z + wA[r].w * x3.w;
        }
    }

    // ---- low-rank epilogue: U rows x S-scaled lr (fully unrolled loads) ----
    {
        const float4* __restrict__ Up  = reinterpret_cast<const float4*>(U + (size_t)o0 * RANK);
        const float4* __restrict__ sl0 = reinterpret_cast<const float4*>(smem + BATCH * DIN);
        const float4* __restrict__ sl1 = sl0 + RANK / 4;
        const float4* __restrict__ sl2 = sl0 + 2 * (RANK / 4);
        const float4* __restrict__ sl3 = sl0 + 3 * (RANK / 4);
#pragma unroll
        for (int k = 0; k < (RANK / 4) / 32; k++) {   // 4 iterations
            const int i = lane + 32 * k;
            const float4 l0 = sl0[i];
            const float4 l1 = sl1[i];
            const float4 l2 = sl2[i];
            const float4 l3 = sl3[i];
#pragma unroll
            for (int r = 0; r < 8; r++) {
                const float4 u4 = Up[(size_t)r * (RANK / 4) + i];
                acc[r][0] += u4.x * l0.x + u4.y * l0.y + u4.z * l0.z + u4.w * l0.w;
                acc[r][1] += u4.x * l1.x + u4.y * l1.y + u4.z * l1.z + u4.w * l1.w;
                acc[r][2] += u4.x * l2.x + u4.y * l2.y + u4.z * l2.z + u4.w * l2.w;
                acc[r][3] += u4.x * l3.x + u4.y * l3.y + u4.z * l3.z + u4.w * l3.w;
            }
        }
    }

    // ---- warp reduction + write ----
#pragma unroll
    for (int r = 0; r < 8; r++)
#pragma unroll
        for (int b = 0; b < 4; b++) {
            float v = acc[r][b];
            v += __shfl_xor_sync(0xffffffffu, v, 16);
            v += __shfl_xor_sync(0xffffffffu, v, 8);
            v += __shfl_xor_sync(0xffffffffu, v, 4);
            v += __shfl_xor_sync(0xffffffffu, v, 2);
            v += __shfl_xor_sync(0xffffffffu, v, 1);
            acc[r][b] = v;
        }

    if (lane == 0) {
#pragma unroll
        for (int r = 0; r < 8; r++) {
            const float bs = bias[o0 + r];
#pragma unroll
            for (int b = 0; b < 4; b++)
                out[(size_t)b * DOUT + o0 + r] = acc[r][b] + bs;
        }
    }
}

// ---------------------------------------------------------------------------
extern "C" void kernel_launch(void* const* d_in, const int* in_sizes, int n_in,
                              void* d_out, int out_size)
{
    const float* input  = (const float*)d_in[0];
    const float* weight = (const float*)d_in[1];
    const float* bias   = (const float*)d_in[2];
    const float* U      = (const float*)d_in[3];
    const float* S      = (const float*)d_in[4];
    const float* V      = (const float*)d_in[5];
    const float* scale  = (const float*)d_in[6];
    const float* thresh = (const float*)d_in[7];
    float* out = (float*)d_out;

    const int smem_bytes = (BATCH * DIN + BATCH * RANK) * (int)sizeof(float); // 73728
    cudaFuncSetAttribute(k_gemv, cudaFuncAttributeMaxDynamicSharedMemorySize, smem_bytes);

    k_mask_lr<<<NCHUNK, 512>>>(input, V, scale, thresh);
    k_lr_reduce<<<RANK / 32, 256>>>(S);
    k_gemv<<<DOUT / 32, 128, smem_bytes>>>(weight, bias, U, out);
}